// round 8
// baseline (speedup 1.0000x reference)
#include <cuda_runtime.h>
#include <cuda_bf16.h>

// LIF over time: x[B=256, T=130, N=4096] f32 -> spikes same shape.
// Recurrence per (b,n): mem = mem*DECAY*(1-spike_prev) + x[t]; spike = mem > THRESH.
// Best measured config (R5): each thread owns TWO 4-neuron column groups
// (c, c+512) of one batch row -> 2 outstanding LDG.128 per thread via 1-deep
// prefetch per group; 128-thread blocks, 1024 CTAs. Streaming cache hints.
// This round: pointer strength reduction in the mainloop.

#define LIF_THRESH 0.6f
#define LIF_DECAY  0.2f

__global__ __launch_bounds__(128)
void lif_kernel(const float4* __restrict__ x, float4* __restrict__ out) {
    constexpr int T    = 130;
    constexpr int ROW4 = 4096 / 4;     // 1024 float4 per (b,t) row
    constexpr int HALF = ROW4 / 2;     // 512: column split per thread

    const int idx = blockIdx.x * blockDim.x + threadIdx.x;   // 0 .. 256*512-1
    const int b   = idx >> 9;          // / 512
    const int c   = idx & (HALF - 1);  // % 512

    const size_t base = (size_t)b * (size_t)(T * ROW4) + (size_t)c;
    const float4* __restrict__ xp = x   + base;
    float4*       __restrict__ op = out + base;

    // group A: column c, group B: column c+HALF
    float a0 = 0.f, a1 = 0.f, a2 = 0.f, a3 = 0.f;
    float b0 = 0.f, b1 = 0.f, b2 = 0.f, b3 = 0.f;
    float fa0 = LIF_DECAY, fa1 = LIF_DECAY, fa2 = LIF_DECAY, fa3 = LIF_DECAY;
    float fb0 = LIF_DECAY, fb1 = LIF_DECAY, fb2 = LIF_DECAY, fb3 = LIF_DECAY;

    float4 curA = __ldcs(xp);
    float4 curB = __ldcs(xp + HALF);
    xp += ROW4;

    #pragma unroll 2
    for (int t = 0; t < T - 1; ++t) {
        // two independent prefetches in flight while the update chains run
        float4 nxtA = __ldcs(xp);
        float4 nxtB = __ldcs(xp + HALF);
        xp += ROW4;

        a0 = fmaf(a0, fa0, curA.x);
        a1 = fmaf(a1, fa1, curA.y);
        a2 = fmaf(a2, fa2, curA.z);
        a3 = fmaf(a3, fa3, curA.w);
        b0 = fmaf(b0, fb0, curB.x);
        b1 = fmaf(b1, fb1, curB.y);
        b2 = fmaf(b2, fb2, curB.z);
        b3 = fmaf(b3, fb3, curB.w);

        float4 spA, spB;
        spA.x = (a0 > LIF_THRESH) ? 1.0f : 0.0f;
        spA.y = (a1 > LIF_THRESH) ? 1.0f : 0.0f;
        spA.z = (a2 > LIF_THRESH) ? 1.0f : 0.0f;
        spA.w = (a3 > LIF_THRESH) ? 1.0f : 0.0f;
        spB.x = (b0 > LIF_THRESH) ? 1.0f : 0.0f;
        spB.y = (b1 > LIF_THRESH) ? 1.0f : 0.0f;
        spB.z = (b2 > LIF_THRESH) ? 1.0f : 0.0f;
        spB.w = (b3 > LIF_THRESH) ? 1.0f : 0.0f;

        fa0 = (a0 > LIF_THRESH) ? 0.0f : LIF_DECAY;
        fa1 = (a1 > LIF_THRESH) ? 0.0f : LIF_DECAY;
        fa2 = (a2 > LIF_THRESH) ? 0.0f : LIF_DECAY;
        fa3 = (a3 > LIF_THRESH) ? 0.0f : LIF_DECAY;
        fb0 = (b0 > LIF_THRESH) ? 0.0f : LIF_DECAY;
        fb1 = (b1 > LIF_THRESH) ? 0.0f : LIF_DECAY;
        fb2 = (b2 > LIF_THRESH) ? 0.0f : LIF_DECAY;
        fb3 = (b3 > LIF_THRESH) ? 0.0f : LIF_DECAY;

        __stcs(op,        spA);
        __stcs(op + HALF, spB);
        op += ROW4;

        curA = nxtA;
        curB = nxtB;
    }

    // tail iteration (t = T-1), no prefetch
    {
        a0 = fmaf(a0, fa0, curA.x);
        a1 = fmaf(a1, fa1, curA.y);
        a2 = fmaf(a2, fa2, curA.z);
        a3 = fmaf(a3, fa3, curA.w);
        b0 = fmaf(b0, fb0, curB.x);
        b1 = fmaf(b1, fb1, curB.y);
        b2 = fmaf(b2, fb2, curB.z);
        b3 = fmaf(b3, fb3, curB.w);

        float4 spA, spB;
        spA.x = (a0 > LIF_THRESH) ? 1.0f : 0.0f;
        spA.y = (a1 > LIF_THRESH) ? 1.0f : 0.0f;
        spA.z = (a2 > LIF_THRESH) ? 1.0f : 0.0f;
        spA.w = (a3 > LIF_THRESH) ? 1.0f : 0.0f;
        spB.x = (b0 > LIF_THRESH) ? 1.0f : 0.0f;
        spB.y = (b1 > LIF_THRESH) ? 1.0f : 0.0f;
        spB.z = (b2 > LIF_THRESH) ? 1.0f : 0.0f;
        spB.w = (b3 > LIF_THRESH) ? 1.0f : 0.0f;

        __stcs(op,        spA);
        __stcs(op + HALF, spB);
    }
}

extern "C" void kernel_launch(void* const* d_in, const int* in_sizes, int n_in,
                              void* d_out, int out_size) {
    const float4* x   = (const float4*)d_in[0];
    float4*       out = (float4*)d_out;

    constexpr int B = 256, N = 4096;
    const int threads = 128;
    const int total   = B * (N / 8);          // 131072 threads (2 groups each)
    const int blocks  = total / threads;      // 1024

    lif_kernel<<<blocks, threads>>>(x, out);
}

// round 10
// speedup vs baseline: 1.0628x; 1.0628x over previous
#include <cuda_runtime.h>
#include <cuda_bf16.h>

// LIF over time: x[B=256, T=130, N=4096] f32 -> spikes same shape.
// Recurrence per (b,n): mem = mem*DECAY*(1-spike_prev) + x[t]; spike = mem > THRESH.
// Each thread owns TWO 4-neuron column groups (c, c+512) of one batch row ->
// 2 outstanding LDG.128 per thread via 1-deep prefetch on each group.
// 128-thread blocks (1024 CTAs). Indexed addressing (t*ROW4), NOT incremented
// pointers — measured faster (R5 vs R8). Streaming cache hints: touch-once data.
// FINAL: exact R5 source (best measured: 171.2us kernel, 76.2% DRAM).

#define LIF_THRESH 0.6f
#define LIF_DECAY  0.2f

__global__ __launch_bounds__(128)
void lif_kernel(const float4* __restrict__ x, float4* __restrict__ out) {
    constexpr int T    = 130;
    constexpr int ROW4 = 4096 / 4;     // 1024 float4 per (b,t) row
    constexpr int HALF = ROW4 / 2;     // 512: column split per thread

    const int idx = blockIdx.x * blockDim.x + threadIdx.x;   // 0 .. 256*512-1
    const int b   = idx >> 9;          // / 512
    const int c   = idx & (HALF - 1);  // % 512

    const size_t base = (size_t)b * (size_t)(T * ROW4) + (size_t)c;
    const float4* __restrict__ xp = x   + base;
    float4*       __restrict__ op = out + base;

    // group A: column c, group B: column c+HALF
    float a0 = 0.f, a1 = 0.f, a2 = 0.f, a3 = 0.f;
    float b0 = 0.f, b1 = 0.f, b2 = 0.f, b3 = 0.f;
    float fa0 = LIF_DECAY, fa1 = LIF_DECAY, fa2 = LIF_DECAY, fa3 = LIF_DECAY;
    float fb0 = LIF_DECAY, fb1 = LIF_DECAY, fb2 = LIF_DECAY, fb3 = LIF_DECAY;

    float4 curA = __ldcs(xp);
    float4 curB = __ldcs(xp + HALF);

    #pragma unroll 2
    for (int t = 0; t < T - 1; ++t) {
        const size_t nofs = (size_t)(t + 1) * ROW4;
        // two independent prefetches in flight while the update chains run
        float4 nxtA = __ldcs(xp + nofs);
        float4 nxtB = __ldcs(xp + nofs + HALF);

        a0 = fmaf(a0, fa0, curA.x);
        a1 = fmaf(a1, fa1, curA.y);
        a2 = fmaf(a2, fa2, curA.z);
        a3 = fmaf(a3, fa3, curA.w);
        b0 = fmaf(b0, fb0, curB.x);
        b1 = fmaf(b1, fb1, curB.y);
        b2 = fmaf(b2, fb2, curB.z);
        b3 = fmaf(b3, fb3, curB.w);

        float4 spA, spB;
        spA.x = (a0 > LIF_THRESH) ? 1.0f : 0.0f;
        spA.y = (a1 > LIF_THRESH) ? 1.0f : 0.0f;
        spA.z = (a2 > LIF_THRESH) ? 1.0f : 0.0f;
        spA.w = (a3 > LIF_THRESH) ? 1.0f : 0.0f;
        spB.x = (b0 > LIF_THRESH) ? 1.0f : 0.0f;
        spB.y = (b1 > LIF_THRESH) ? 1.0f : 0.0f;
        spB.z = (b2 > LIF_THRESH) ? 1.0f : 0.0f;
        spB.w = (b3 > LIF_THRESH) ? 1.0f : 0.0f;

        fa0 = (a0 > LIF_THRESH) ? 0.0f : LIF_DECAY;
        fa1 = (a1 > LIF_THRESH) ? 0.0f : LIF_DECAY;
        fa2 = (a2 > LIF_THRESH) ? 0.0f : LIF_DECAY;
        fa3 = (a3 > LIF_THRESH) ? 0.0f : LIF_DECAY;
        fb0 = (b0 > LIF_THRESH) ? 0.0f : LIF_DECAY;
        fb1 = (b1 > LIF_THRESH) ? 0.0f : LIF_DECAY;
        fb2 = (b2 > LIF_THRESH) ? 0.0f : LIF_DECAY;
        fb3 = (b3 > LIF_THRESH) ? 0.0f : LIF_DECAY;

        const size_t ofs = (size_t)t * ROW4;
        __stcs(op + ofs,        spA);
        __stcs(op + ofs + HALF, spB);

        curA = nxtA;
        curB = nxtB;
    }

    // tail iteration (t = T-1), no prefetch
    {
        a0 = fmaf(a0, fa0, curA.x);
        a1 = fmaf(a1, fa1, curA.y);
        a2 = fmaf(a2, fa2, curA.z);
        a3 = fmaf(a3, fa3, curA.w);
        b0 = fmaf(b0, fb0, curB.x);
        b1 = fmaf(b1, fb1, curB.y);
        b2 = fmaf(b2, fb2, curB.z);
        b3 = fmaf(b3, fb3, curB.w);

        float4 spA, spB;
        spA.x = (a0 > LIF_THRESH) ? 1.0f : 0.0f;
        spA.y = (a1 > LIF_THRESH) ? 1.0f : 0.0f;
        spA.z = (a2 > LIF_THRESH) ? 1.0f : 0.0f;
        spA.w = (a3 > LIF_THRESH) ? 1.0f : 0.0f;
        spB.x = (b0 > LIF_THRESH) ? 1.0f : 0.0f;
        spB.y = (b1 > LIF_THRESH) ? 1.0f : 0.0f;
        spB.z = (b2 > LIF_THRESH) ? 1.0f : 0.0f;
        spB.w = (b3 > LIF_THRESH) ? 1.0f : 0.0f;

        const size_t ofs = (size_t)(T - 1) * ROW4;
        __stcs(op + ofs,        spA);
        __stcs(op + ofs + HALF, spB);
    }
}

extern "C" void kernel_launch(void* const* d_in, const int* in_sizes, int n_in,
                              void* d_out, int out_size) {
    const float4* x   = (const float4*)d_in[0];
    float4*       out = (float4*)d_out;

    constexpr int B = 256, N = 4096;
    const int threads = 128;
    const int total   = B * (N / 8);          // 131072 threads (2 groups each)
    const int blocks  = total / threads;      // 1024

    lif_kernel<<<blocks, threads>>>(x, out);
}